// round 5
// baseline (speedup 1.0000x reference)
#include <cuda_runtime.h>
#include <math.h>
#include <cstdint>

#define N_NODES 8192
#define FIN 128
#define FOUT 64
#define NB 72              // 64 feats + ones col + 7 pad
#define TILE_M 32
#define JTILES 32          // j-tiles per CTA (j-split = 2, 128 cols each)
#define NSTAGE 3
#define LRELU_ALPHA 0.2f

#define P_STRIDE 132
#define P_BYTES (TILE_M * P_STRIDE * 4)     // 16896
#define SMEM_BYTES (NSTAGE * P_BYTES)       // 50688
#define PART_STRIDE 66

// ---------------- device scratch (no allocation allowed) -------------------
__device__ __align__(256) float g_Bpack[1024 * (NB * 8)];        // 2.36 MB
__device__ __align__(256) float g_part[512 * TILE_M * PART_STRIDE]; // 4.3 MB
__device__ float g_s1[N_NODES];
__device__ float g_s2[N_NODES];

// ---------------- helpers ----------------------------------------------------
__device__ __forceinline__ uint32_t smem_u32(const void* p) {
    uint32_t a;
    asm("{ .reg .u64 t; cvta.to.shared.u64 t, %1; cvt.u32.u64 %0, t; }" : "=r"(a) : "l"(p));
    return a;
}
__device__ __forceinline__ uint32_t f2tf32(float x) {
    uint32_t u;
    asm("cvt.rna.tf32.f32 %0, %1;" : "=r"(u) : "f"(x));
    return u;
}
__device__ __forceinline__ uint32_t lds32(uint32_t a) {
    uint32_t v; asm("ld.shared.b32 %0, [%1];" : "=r"(v) : "r"(a)); return v;
}
__device__ __forceinline__ void sts128(uint32_t a, uint32_t v0, uint32_t v1, uint32_t v2, uint32_t v3) {
    asm volatile("st.shared.v4.b32 [%0], {%1,%2,%3,%4};" :: "r"(a), "r"(v0), "r"(v1), "r"(v2), "r"(v3) : "memory");
}
#define BAR_SYNC(id)   asm volatile("bar.sync %0, 256;"   :: "r"(id) : "memory")
#define BAR_ARRIVE(id) asm volatile("bar.arrive %0, 256;" :: "r"(id) : "memory")

__device__ __forceinline__ void mma_tf32(float* c,
                                         uint32_t a0, uint32_t a1, uint32_t a2, uint32_t a3,
                                         uint32_t b0, uint32_t b1) {
    asm("mma.sync.aligned.m16n8k8.row.col.f32.tf32.tf32.f32 "
        "{%0,%1,%2,%3},{%4,%5,%6,%7},{%8,%9},{%0,%1,%2,%3};"
        : "+f"(c[0]), "+f"(c[1]), "+f"(c[2]), "+f"(c[3])
        : "r"(a0), "r"(a1), "r"(a2), "r"(a3), "r"(b0), "r"(b1));
}

// ---------------------------------------------------------------------------
// Kernel 1: Wh = h@W -> g_Bpack (mma B-fragment order, tf32) ; s1, s2.
//   j = jt*128 + ks*8 + sel*4 + tig ; layout [jt*16+ks][n][tig][sel]
// ---------------------------------------------------------------------------
__global__ __launch_bounds__(64) void wh_kernel(const float* __restrict__ h,
                                                const float* __restrict__ W,
                                                const float* __restrict__ a) {
    __shared__ float sh[FIN];
    __shared__ float red1[2], red2[2];
    const int i = blockIdx.x;
    const int f = threadIdx.x;

    sh[f]      = h[(size_t)i * FIN + f];
    sh[f + 64] = h[(size_t)i * FIN + f + 64];
    __syncthreads();

    float acc = 0.f;
#pragma unroll
    for (int k = 0; k < FIN; k++)
        acc = fmaf(sh[k], W[k * FOUT + f], acc);

    const int jt  = i >> 7;
    const int ks  = (i >> 3) & 15;
    const int sel = (i >> 2) & 1;
    const int tig = i & 3;
    const size_t base = (size_t)(jt * 16 + ks) * (NB * 8) + tig * 2 + sel;
    g_Bpack[base + (size_t)f * 8] = __uint_as_float(f2tf32(acc));
    if (f < 8)
        g_Bpack[base + (size_t)(64 + f) * 8] = (f == 0) ? 1.0f : 0.0f;

    float v1 = acc * a[f];
    float v2 = acc * a[FOUT + f];
#pragma unroll
    for (int o = 16; o > 0; o >>= 1) {
        v1 += __shfl_xor_sync(0xFFFFFFFFu, v1, o);
        v2 += __shfl_xor_sync(0xFFFFFFFFu, v2, o);
    }
    if ((f & 31) == 0) { red1[f >> 5] = v1; red2[f >> 5] = v2; }
    __syncthreads();
    if (f == 0) {
        g_s1[i] = red1[0] + red1[1];
        g_s2[i] = red2[0] + red2[1];
    }
}

// ---------------------------------------------------------------------------
// Consumer: one warp owns m16 x n(NF*8) of D[32 x 72].
// ---------------------------------------------------------------------------
template <int NF, int NHALF>
__device__ __forceinline__ void consumer_loop(uint32_t sbase, int mh, int lane,
                                              int half, int cta) {
    const int g   = lane >> 2;
    const int tig = lane & 3;
    const uint32_t aoff0 = (uint32_t)((mh * 16 + g) * P_STRIDE + tig) * 4;
    const float* __restrict__ bbase = g_Bpack + (NHALF * 40 + g) * 8 + tig * 2
                                    + (size_t)(half * JTILES) * 16 * (NB * 8);

    float C[NF][4];
#pragma unroll
    for (int n = 0; n < NF; n++)
#pragma unroll
        for (int q = 0; q < 4; q++) C[n][q] = 0.f;

    int s = 0;
    for (int t = 0; t < JTILES; t++) {
        BAR_SYNC(1 + s);
        const uint32_t pb = sbase + (uint32_t)s * P_BYTES;
        const float* __restrict__ kb = bbase + (size_t)t * 16 * (NB * 8);
#pragma unroll
        for (int ks = 0; ks < 16; ks++) {
            const uint32_t pa0 = pb + aoff0 + (uint32_t)ks * 32;
            uint32_t A[4];
            A[0] = lds32(pa0);        A[1] = lds32(pa0 + 8u * P_STRIDE * 4);
            A[2] = lds32(pa0 + 16);   A[3] = lds32(pa0 + 8u * P_STRIDE * 4 + 16);
            const float* bp = kb + ks * (NB * 8);
#pragma unroll
            for (int nf = 0; nf < NF; nf++) {
                const float2 bf = *(const float2*)(bp + nf * 64);
                mma_tf32(C[nf], A[0], A[1], A[2], A[3],
                         __float_as_uint(bf.x), __float_as_uint(bf.y));
            }
        }
        if (t < JTILES - NSTAGE) BAR_ARRIVE(4 + s);
        s = (s == NSTAGE - 1) ? 0 : s + 1;
    }

    // store partials (numerator cols 0..63, denominator col 64)
    float* pbase = g_part + (size_t)cta * TILE_M * PART_STRIDE;
    const int r1 = mh * 16 + g;
    float* prow1 = pbase + r1 * PART_STRIDE;
    float* prow2 = prow1 + 8 * PART_STRIDE;
#pragma unroll
    for (int nf = 0; nf < NF; nf++) {
        const int gcol = NHALF * 40 + nf * 8 + 2 * tig;
        if (gcol < 64) {
            *(float2*)(prow1 + gcol) = make_float2(C[nf][0], C[nf][1]);
            *(float2*)(prow2 + gcol) = make_float2(C[nf][2], C[nf][3]);
        } else if (gcol == 64) {
            prow1[64] = C[nf][0];
            prow2[64] = C[nf][2];
        }
    }
}

// ---------------------------------------------------------------------------
// Kernel 2: warp-specialized.  grid = 512 (256 row-blocks x 2 j-halves),
// 4 CTAs/SM.  warps 0-3: mma consumers.  warps 4-7: P-tile producers.
// ---------------------------------------------------------------------------
__global__ __launch_bounds__(256, 4) void attn_mma_kernel(const int*   __restrict__ adj,
                                                          const float* __restrict__ efeat,
                                                          const float* __restrict__ a) {
    extern __shared__ char smem[];
    const uint32_t sbase = smem_u32(smem);
    const int tid  = threadIdx.x;
    const int wid  = tid >> 5;
    const int lane = tid & 31;
    const int cta  = blockIdx.x;
    const int i0   = (cta >> 1) * TILE_M;
    const int half = cta & 1;

    if (wid < 4) {
        const int mh = wid & 1;
        if ((wid >> 1) == 0) consumer_loop<5, 0>(sbase, mh, lane, half, cta);
        else                 consumer_loop<4, 1>(sbase, mh, lane, half, cta);
    } else {
        // ================= PRODUCER =================
        const int ptid = tid - 128;
        const int r    = ptid >> 2;               // row 0..31
        const int col0 = (ptid & 3) * 32;
        const float ae = a[2 * FOUT];
        const int grow = i0 + r;
        const float s1 = g_s1[grow];

        int s = 0;
        for (int t = 0; t < JTILES; t++) {
            const int jb = half * 4096 + (t << 7);
            if (t >= NSTAGE) BAR_SYNC(4 + s);
            const float4* __restrict__ s2p = (const float4*)(g_s2 + jb + col0);
            const int4*   __restrict__ pa = (const int4*)  (adj   + (size_t)grow * N_NODES + jb + col0);
            const float4* __restrict__ pe = (const float4*)(efeat + (size_t)grow * N_NODES + jb + col0);
            const uint32_t prow = sbase + (uint32_t)s * P_BYTES
                                + (uint32_t)(r * P_STRIDE + col0) * 4;
#pragma unroll
            for (int k = 0; k < 8; k++) {
                const int4   av = __ldcs(pa + k);
                const float4 ev = __ldcs(pe + k);
                const float4 sv = s2p[k];
                float e0 = fmaf(ev.x, ae, s1 + sv.x);
                float e1 = fmaf(ev.y, ae, s1 + sv.y);
                float e2 = fmaf(ev.z, ae, s1 + sv.z);
                float e3 = fmaf(ev.w, ae, s1 + sv.w);
                e0 = fmaxf(e0, LRELU_ALPHA * e0);
                e1 = fmaxf(e1, LRELU_ALPHA * e1);
                e2 = fmaxf(e2, LRELU_ALPHA * e2);
                e3 = fmaxf(e3, LRELU_ALPHA * e3);
                const uint32_t u0 = (av.x > 0) ? f2tf32(__expf(e0)) : 0u;
                const uint32_t u1 = (av.y > 0) ? f2tf32(__expf(e1)) : 0u;
                const uint32_t u2 = (av.z > 0) ? f2tf32(__expf(e2)) : 0u;
                const uint32_t u3 = (av.w > 0) ? f2tf32(__expf(e3)) : 0u;
                sts128(prow + (uint32_t)k * 16, u0, u1, u2, u3);
            }
            BAR_ARRIVE(1 + s);
            s = (s == NSTAGE - 1) ? 0 : s + 1;
        }
    }
}

// ---------------------------------------------------------------------------
// Kernel 3: combine the two j-half partials, divide, ELU, store.
// ---------------------------------------------------------------------------
__global__ __launch_bounds__(256) void combine_kernel(float* __restrict__ out) {
    const int idx = blockIdx.x * 256 + threadIdx.x;   // 8192*32
    const int i   = idx >> 5;
    const int f2  = idx & 31;
    const int rowblk = i >> 5;                        // 32-row blocks
    const int r      = i & 31;
    const float* p0 = g_part + ((size_t)(rowblk * 2) * TILE_M + r) * PART_STRIDE;
    const float* p1 = p0 + TILE_M * PART_STRIDE;
    const float inv = 1.f / (p0[64] + p1[64]);
    const float2 a0 = *(const float2*)(p0 + f2 * 2);
    const float2 b0 = *(const float2*)(p1 + f2 * 2);
    float v0 = (a0.x + b0.x) * inv;
    float v1 = (a0.y + b0.y) * inv;
    v0 = (v0 > 0.f) ? v0 : expm1f(v0);
    v1 = (v1 > 0.f) ? v1 : expm1f(v1);
    *(float2*)(out + (size_t)i * FOUT + f2 * 2) = make_float2(v0, v1);
}

// ---------------------------------------------------------------------------
extern "C" void kernel_launch(void* const* d_in, const int* in_sizes, int n_in,
                              void* d_out, int out_size) {
    const float* h     = (const float*)d_in[0];   // [8192,128]
    const int*   adj   = (const int*)  d_in[1];   // [8192,8192]
    const float* efeat = (const float*)d_in[2];   // [8192,8192]
    const float* W     = (const float*)d_in[3];   // [128,64]
    const float* a     = (const float*)d_in[4];   // [129,1]
    float* out = (float*)d_out;                   // [8192,64]

    cudaFuncSetAttribute(attn_mma_kernel,
                         cudaFuncAttributeMaxDynamicSharedMemorySize, SMEM_BYTES);

    wh_kernel<<<N_NODES, 64>>>(h, W, a);
    attn_mma_kernel<<<512, 256, SMEM_BYTES>>>(adj, efeat, a);
    combine_kernel<<<1024, 256>>>(out);
}

// round 6
// speedup vs baseline: 1.7180x; 1.7180x over previous
#include <cuda_runtime.h>
#include <cuda_bf16.h>
#include <math.h>
#include <cstdint>

#define N_NODES 8192
#define FIN 128
#define FOUT 64
#define TILE_M 64
#define JTILES 32          // 32 tiles x 128 cols = 4096 cols (j-split = 2)
#define NSTAGE 3
#define LRELU_ALPHA 0.2f

#define P_ROW 272                          // 128 bf16 + pad (136 halves)
#define P_BYTES (TILE_M * P_ROW)           // 17408
#define B_KS_U32 576                       // per kstep: 72 n * 4 tig * 2 pair
#define B_BYTES (8 * B_KS_U32 * 4)         // 18432
#define STAGE_BYTES (P_BYTES + B_BYTES)    // 35840
#define SMEM_BYTES (NSTAGE * STAGE_BYTES)  // 107520
#define PART_STRIDE 66

// ---------------- device scratch (no allocation allowed) -------------------
__device__ __align__(256) uint32_t g_Bpack[64 * 8 * B_KS_U32];      // 1.18 MB
__device__ __align__(256) uint32_t g_mask[N_NODES * 256];           // 8 MB
__device__ __align__(256) float g_part[256 * TILE_M * PART_STRIDE]; // 4.3 MB
__device__ float g_s1[N_NODES];
__device__ float g_s2[N_NODES];

// ---------------- helpers ----------------------------------------------------
__device__ __forceinline__ uint32_t smem_u32(const void* p) {
    uint32_t a;
    asm("{ .reg .u64 t; cvta.to.shared.u64 t, %1; cvt.u32.u64 %0, t; }" : "=r"(a) : "l"(p));
    return a;
}
__device__ __forceinline__ uint32_t lds32(uint32_t a) {
    uint32_t v; asm("ld.shared.b32 %0, [%1];" : "=r"(v) : "r"(a)); return v;
}
__device__ __forceinline__ uint2 lds64(uint32_t a) {
    uint2 v; asm("ld.shared.v2.b32 {%0,%1}, [%2];" : "=r"(v.x), "=r"(v.y) : "r"(a)); return v;
}
__device__ __forceinline__ void sts128(uint32_t a, uint32_t v0, uint32_t v1, uint32_t v2, uint32_t v3) {
    asm volatile("st.shared.v4.b32 [%0], {%1,%2,%3,%4};" :: "r"(a), "r"(v0), "r"(v1), "r"(v2), "r"(v3) : "memory");
}
__device__ __forceinline__ void cp16(uint32_t dst, const void* src) {
    asm volatile("cp.async.cg.shared.global [%0], [%1], 16;" :: "r"(dst), "l"(src) : "memory");
}
#define CP_COMMIT() asm volatile("cp.async.commit_group;" ::: "memory")
#define CP_WAIT0()  asm volatile("cp.async.wait_group 0;" ::: "memory")
#define BAR_SYNC(id)   asm volatile("bar.sync %0, 256;"   :: "r"(id) : "memory")
#define BAR_ARRIVE(id) asm volatile("bar.arrive %0, 256;" :: "r"(id) : "memory")

__device__ __forceinline__ void mma_bf16(float* c,
                                         uint32_t a0, uint32_t a1, uint32_t a2, uint32_t a3,
                                         uint32_t b0, uint32_t b1) {
    asm("mma.sync.aligned.m16n8k16.row.col.f32.bf16.bf16.f32 "
        "{%0,%1,%2,%3},{%4,%5,%6,%7},{%8,%9},{%0,%1,%2,%3};"
        : "+f"(c[0]), "+f"(c[1]), "+f"(c[2]), "+f"(c[3])
        : "r"(a0), "r"(a1), "r"(a2), "r"(a3), "r"(b0), "r"(b1));
}

// ---------------------------------------------------------------------------
// Kernel 0: pack adj > 0 into bitmask (bit b of word w on row i <=> adj[i][32w+b])
// ---------------------------------------------------------------------------
__global__ __launch_bounds__(256) void pack_kernel(const int* __restrict__ adj) {
    const int wid  = threadIdx.x >> 5;
    const int lane = threadIdx.x & 31;
    const int row  = blockIdx.x * 8 + wid;
    const int4* __restrict__ arow = (const int4*)(adj + (size_t)row * N_NODES);
    uint32_t* mrow = g_mask + (size_t)row * 256;
#pragma unroll 4
    for (int it = 0; it < 64; it++) {
        const int4 v = __ldcs(arow + it * 32 + lane);
        uint32_t b = (uint32_t)(v.x > 0) | ((uint32_t)(v.y > 0) << 1)
                   | ((uint32_t)(v.z > 0) << 2) | ((uint32_t)(v.w > 0) << 3);
        b <<= (lane & 7) * 4;
        b |= __shfl_xor_sync(0xFFFFFFFFu, b, 1);
        b |= __shfl_xor_sync(0xFFFFFFFFu, b, 2);
        b |= __shfl_xor_sync(0xFFFFFFFFu, b, 4);
        if ((lane & 7) == 0) mrow[it * 4 + (lane >> 3)] = b;
    }
}

// ---------------------------------------------------------------------------
// Kernel 1: Wh = h@W -> g_Bpack (bf16 mma m16n8k16 B-fragment order) ; s1, s2.
//  j = jt*128 + ks*16 + ko ; ko = pair*8 + tig*2 + b
//  bf16 elem index = ((jt*8+ks)*576 + (n*4+tig)*2 + pair)*2 + b
// ---------------------------------------------------------------------------
__global__ __launch_bounds__(64) void wh_kernel(const float* __restrict__ h,
                                                const float* __restrict__ W,
                                                const float* __restrict__ a) {
    __shared__ float sh[FIN];
    __shared__ float red1[2], red2[2];
    const int i = blockIdx.x;
    const int f = threadIdx.x;

    sh[f]      = h[(size_t)i * FIN + f];
    sh[f + 64] = h[(size_t)i * FIN + f + 64];
    __syncthreads();

    float acc0 = 0.f, acc1 = 0.f;
#pragma unroll
    for (int k = 0; k < FIN; k += 2) {
        acc0 = fmaf(sh[k],     W[k * FOUT + f],       acc0);
        acc1 = fmaf(sh[k + 1], W[(k + 1) * FOUT + f], acc1);
    }
    const float acc = acc0 + acc1;

    const int jt   = i >> 7;
    const int rem  = i & 127;
    const int ks   = rem >> 4;
    const int ko   = rem & 15;
    const int pair = ko >> 3;
    const int tig  = (ko & 7) >> 1;
    const int b    = ko & 1;
    __nv_bfloat16* bp = (__nv_bfloat16*)g_Bpack;
    const size_t sbase = (size_t)(jt * 8 + ks) * (B_KS_U32 * 2);
    bp[sbase + ((f * 4 + tig) * 2 + pair) * 2 + b] = __float2bfloat16(acc);
    if (f < 8) {
        const float ov = (f == 0) ? 1.0f : 0.0f;  // col 64 = ones (denominator)
        bp[sbase + (((64 + f) * 4 + tig) * 2 + pair) * 2 + b] = __float2bfloat16(ov);
    }

    float v1 = acc * a[f];
    float v2 = acc * a[FOUT + f];
#pragma unroll
    for (int o = 16; o > 0; o >>= 1) {
        v1 += __shfl_xor_sync(0xFFFFFFFFu, v1, o);
        v2 += __shfl_xor_sync(0xFFFFFFFFu, v2, o);
    }
    if ((f & 31) == 0) { red1[f >> 5] = v1; red2[f >> 5] = v2; }
    __syncthreads();
    if (f == 0) {
        g_s1[i] = red1[0] + red1[1];
        g_s2[i] = red2[0] + red2[1];
    }
}

// ---------------------------------------------------------------------------
// Consumer: bf16 mma, one warp owns mhalf (32 rows) x n(NF*8).
// ---------------------------------------------------------------------------
template <int NF, int NHALF>
__device__ __forceinline__ void consumer_loop(uint32_t sbase, int mh, int lane, int cta) {
    const int g   = lane >> 2;
    const int tig = lane & 3;
    const uint32_t aoff = (uint32_t)((mh * 32 + g) * P_ROW + tig * 4);
    const uint32_t boff = (uint32_t)(((NHALF * 40 + g) * 4 + tig) * 8);

    float C[2][NF][4];
#pragma unroll
    for (int m = 0; m < 2; m++)
#pragma unroll
        for (int n = 0; n < NF; n++)
#pragma unroll
            for (int q = 0; q < 4; q++) C[m][n][q] = 0.f;

    int s = 0;
    for (int t = 0; t < JTILES; t++) {
        BAR_SYNC(1 + s);
        const uint32_t pb = sbase + (uint32_t)s * STAGE_BYTES;
        const uint32_t bb = pb + P_BYTES + boff;
#pragma unroll
        for (int ks = 0; ks < 8; ks++) {
            const uint32_t pa0 = pb + aoff + (uint32_t)ks * 32;
            const uint32_t pa1 = pa0 + 16u * P_ROW;
            uint32_t A0[4], A1[4];
            A0[0] = lds32(pa0);       A0[1] = lds32(pa0 + 8u * P_ROW);
            A0[2] = lds32(pa0 + 16);  A0[3] = lds32(pa0 + 8u * P_ROW + 16);
            A1[0] = lds32(pa1);       A1[1] = lds32(pa1 + 8u * P_ROW);
            A1[2] = lds32(pa1 + 16);  A1[3] = lds32(pa1 + 8u * P_ROW + 16);
            const uint32_t bk = bb + (uint32_t)ks * (B_KS_U32 * 4);
#pragma unroll
            for (int nf = 0; nf < NF; nf++) {
                const uint2 bf = lds64(bk + (uint32_t)nf * 256);
                mma_bf16(C[0][nf], A0[0], A0[1], A0[2], A0[3], bf.x, bf.y);
                mma_bf16(C[1][nf], A1[0], A1[1], A1[2], A1[3], bf.x, bf.y);
            }
        }
        if (t < JTILES - NSTAGE) BAR_ARRIVE(4 + s);
        s = (s == NSTAGE - 1) ? 0 : s + 1;
    }

    // store partials (numerator cols 0..63, denominator col 64)
    float* pbase = g_part + (size_t)cta * TILE_M * PART_STRIDE;
#pragma unroll
    for (int m = 0; m < 2; m++) {
        const int r1 = mh * 32 + m * 16 + g;
        float* prow1 = pbase + r1 * PART_STRIDE;
        float* prow2 = prow1 + 8 * PART_STRIDE;
#pragma unroll
        for (int nf = 0; nf < NF; nf++) {
            const int gcol = NHALF * 40 + nf * 8 + 2 * tig;
            if (gcol < 64) {
                *(float2*)(prow1 + gcol) = make_float2(C[m][nf][0], C[m][nf][1]);
                *(float2*)(prow2 + gcol) = make_float2(C[m][nf][2], C[m][nf][3]);
            } else if (gcol == 64) {
                prow1[64] = C[m][nf][0];
                prow2[64] = C[m][nf][2];
            }
        }
    }
}

// ---------------------------------------------------------------------------
// Kernel 2: warp-specialized.  grid = 256 (128 row-blocks x 2 j-halves),
// 2 CTAs/SM.  warps 0-3: bf16 mma consumers.  warps 4-7: producers
// (masked exp -> bf16 P in SMEM; cp.async B tile into SMEM).
// ---------------------------------------------------------------------------
__global__ __launch_bounds__(256, 2) void attn_mma_kernel(const float* __restrict__ efeat,
                                                          const float* __restrict__ a) {
    extern __shared__ char smem[];
    const uint32_t sbase = smem_u32(smem);
    const int tid  = threadIdx.x;
    const int wid  = tid >> 5;
    const int lane = tid & 31;
    const int cta  = blockIdx.x;
    const int i0   = (cta >> 1) * TILE_M;
    const int half = cta & 1;

    if (wid < 4) {
        const int mh = wid & 1;
        if ((wid >> 1) == 0) consumer_loop<5, 0>(sbase, mh, lane, cta);
        else                 consumer_loop<4, 1>(sbase, mh, lane, cta);
    } else {
        // ================= PRODUCER =================
        const int ptid = tid - 128;
        const int r    = ptid >> 2;               // row 0..31 (pass 0), +32 (pass 1)
        const int colq = ptid & 3;
        const int col0 = colq * 32;
        const float ae = a[2 * FOUT];
        const int g0 = i0 + r, g1 = g0 + 32;
        const float s1a = g_s1[g0];
        const float s1b = g_s1[g1];
        const uint32_t* mrow0 = g_mask + (size_t)g0 * 256;
        const uint32_t* mrow1 = g_mask + (size_t)g1 * 256;

        int s = 0;
        for (int t = 0; t < JTILES; t++) {
            const int jb = half * 4096 + (t << 7);
            if (t >= NSTAGE) BAR_SYNC(4 + s);

            // ---- B tile cp.async (18432 B, 9x16B per thread) ----
            {
                const char* src = (const char*)g_Bpack + (size_t)(half * 32 + t) * B_BYTES;
                const uint32_t bdst = sbase + (uint32_t)s * STAGE_BYTES + P_BYTES;
#pragma unroll
                for (int q = 0; q < 9; q++) {
                    const int idx = ptid + q * 128;
                    cp16(bdst + (uint32_t)idx * 16, src + (size_t)idx * 16);
                }
                CP_COMMIT();
            }

            const uint32_t woff = (uint32_t)(half * 128 + t * 4 + colq);
            const uint32_t m0 = mrow0[woff];
            const uint32_t m1 = mrow1[woff];
            const float4* __restrict__ s2p = (const float4*)(g_s2 + jb + col0);
            float4 s2c[8];
#pragma unroll
            for (int k = 0; k < 8; k++) s2c[k] = s2p[k];

#pragma unroll
            for (int pass = 0; pass < 2; pass++) {
                const int grow = pass ? g1 : g0;
                const float s1 = pass ? s1b : s1a;
                const uint32_t mw = pass ? m1 : m0;
                const float4* __restrict__ pe = (const float4*)(efeat + (size_t)grow * N_NODES + jb + col0);
                const uint32_t prow = sbase + (uint32_t)s * STAGE_BYTES
                                    + (uint32_t)((r + pass * 32) * P_ROW + col0 * 2);
                uint32_t buf[4];
#pragma unroll
                for (int k = 0; k < 8; k++) {
                    const float4 ev = __ldcs(pe + k);
                    const float4 sv = s2c[k];
                    float e0 = fmaf(ev.x, ae, s1 + sv.x);
                    float e1 = fmaf(ev.y, ae, s1 + sv.y);
                    float e2 = fmaf(ev.z, ae, s1 + sv.z);
                    float e3 = fmaf(ev.w, ae, s1 + sv.w);
                    e0 = fmaxf(e0, LRELU_ALPHA * e0);
                    e1 = fmaxf(e1, LRELU_ALPHA * e1);
                    e2 = fmaxf(e2, LRELU_ALPHA * e2);
                    e3 = fmaxf(e3, LRELU_ALPHA * e3);
                    const float p0 = (mw & (1u << (k * 4 + 0))) ? __expf(e0) : 0.f;
                    const float p1 = (mw & (1u << (k * 4 + 1))) ? __expf(e1) : 0.f;
                    const float p2 = (mw & (1u << (k * 4 + 2))) ? __expf(e2) : 0.f;
                    const float p3 = (mw & (1u << (k * 4 + 3))) ? __expf(e3) : 0.f;
                    const __nv_bfloat162 lo = __floats2bfloat162_rn(p0, p1);
                    const __nv_bfloat162 hi = __floats2bfloat162_rn(p2, p3);
                    buf[(k & 1) * 2 + 0] = *(const uint32_t*)&lo;
                    buf[(k & 1) * 2 + 1] = *(const uint32_t*)&hi;
                    if (k & 1)
                        sts128(prow + (uint32_t)(k >> 1) * 16, buf[0], buf[1], buf[2], buf[3]);
                }
            }
            CP_WAIT0();
            BAR_ARRIVE(1 + s);
            s = (s == NSTAGE - 1) ? 0 : s + 1;
        }
    }
}

// ---------------------------------------------------------------------------
// Kernel 3: combine the two j-half partials, divide, ELU, store.
// ---------------------------------------------------------------------------
__global__ __launch_bounds__(256) void combine_kernel(float* __restrict__ out) {
    const int idx = blockIdx.x * 256 + threadIdx.x;   // 8192*32
    const int i   = idx >> 5;
    const int f2  = idx & 31;
    const float* p0 = g_part + ((size_t)(i >> 6) * 2 * TILE_M + (i & 63)) * PART_STRIDE;
    const float* p1 = p0 + TILE_M * PART_STRIDE;
    const float inv = 1.f / (p0[64] + p1[64]);
    const float2 a0 = *(const float2*)(p0 + f2 * 2);
    const float2 b0 = *(const float2*)(p1 + f2 * 2);
    float v0 = (a0.x + b0.x) * inv;
    float v1 = (a0.y + b0.y) * inv;
    v0 = (v0 > 0.f) ? v0 : expm1f(v0);
    v1 = (v1 > 0.f) ? v1 : expm1f(v1);
    *(float2*)(out + (size_t)i * FOUT + f2 * 2) = make_float2(v0, v1);
}

// ---------------------------------------------------------------------------
extern "C" void kernel_launch(void* const* d_in, const int* in_sizes, int n_in,
                              void* d_out, int out_size) {
    const float* h     = (const float*)d_in[0];   // [8192,128]
    const int*   adj   = (const int*)  d_in[1];   // [8192,8192]
    const float* efeat = (const float*)d_in[2];   // [8192,8192]
    const float* W     = (const float*)d_in[3];   // [128,64]
    const float* a     = (const float*)d_in[4];   // [129,1]
    float* out = (float*)d_out;                   // [8192,64]

    cudaFuncSetAttribute(attn_mma_kernel,
                         cudaFuncAttributeMaxDynamicSharedMemorySize, SMEM_BYTES);

    pack_kernel<<<N_NODES / 8, 256>>>(adj);
    wh_kernel<<<N_NODES, 64>>>(h, W, a);
    attn_mma_kernel<<<256, 256, SMEM_BYTES>>>(efeat, a);
    combine_kernel<<<1024, 256>>>(out);
}

// round 8
// speedup vs baseline: 2.0686x; 1.2041x over previous
#include <cuda_runtime.h>
#include <cuda_bf16.h>
#include <math.h>
#include <cstdint>

#define N_NODES 8192
#define FIN 128
#define FOUT 64
#define TILE_M 64
#define JTILES 64          // 64 tiles x 64 cols = 4096 cols (j-split = 2)
#define LRELU_ALPHA 0.2f

// SMEM: [0,16384) s2 slice ; 3 stages of (E 18432 + P 9216)
#define S2_SZ 16384
#define E_SZ 18432          // 128 producer threads x 144 B (32 floats + 16B pad)
#define P_SZ 9216           // 64 rows x 144 B (128 bf16 data + 16 pad)
#define STAGE_SZ (E_SZ + P_SZ)               // 27648
#define SMEM_BYTES (S2_SZ + 3 * STAGE_SZ)    // 99328
#define PART_STRIDE 66
#define B_TILE_BYTES 9216   // 4 ksteps x 2304 B

// ---------------- device scratch (no allocation allowed) -------------------
__device__ __align__(256) uint32_t g_Bpack[512 * 576];              // 1.18 MB
__device__ __align__(256) uint32_t g_mask[N_NODES * 256];           // 8 MB
__device__ __align__(256) float g_part[256 * TILE_M * PART_STRIDE]; // 4.3 MB
__device__ float g_s1[N_NODES];
__device__ float g_s2[N_NODES];

// ---------------- helpers ----------------------------------------------------
__device__ __forceinline__ uint32_t smem_u32(const void* p) {
    uint32_t a;
    asm("{ .reg .u64 t; cvta.to.shared.u64 t, %1; cvt.u32.u64 %0, t; }" : "=r"(a) : "l"(p));
    return a;
}
__device__ __forceinline__ uint32_t lds32(uint32_t a) {
    uint32_t v; asm("ld.shared.b32 %0, [%1];" : "=r"(v) : "r"(a)); return v;
}
__device__ __forceinline__ float4 lds128f(uint32_t a) {
    float4 v;
    asm("ld.shared.v4.f32 {%0,%1,%2,%3}, [%4];"
        : "=f"(v.x), "=f"(v.y), "=f"(v.z), "=f"(v.w) : "r"(a));
    return v;
}
__device__ __forceinline__ void sts128(uint32_t a, uint32_t v0, uint32_t v1, uint32_t v2, uint32_t v3) {
    asm volatile("st.shared.v4.b32 [%0], {%1,%2,%3,%4};" :: "r"(a), "r"(v0), "r"(v1), "r"(v2), "r"(v3) : "memory");
}
__device__ __forceinline__ void cp16(uint32_t dst, const void* src) {
    asm volatile("cp.async.cg.shared.global [%0], [%1], 16;" :: "r"(dst), "l"(src) : "memory");
}
#define CP_COMMIT() asm volatile("cp.async.commit_group;" ::: "memory")
#define CP_WAIT1()  asm volatile("cp.async.wait_group 1;" ::: "memory")
#define BAR_SYNC(id)   asm volatile("bar.sync %0, 256;"   :: "r"(id) : "memory")
#define BAR_ARRIVE(id) asm volatile("bar.arrive %0, 256;" :: "r"(id) : "memory")

__device__ __forceinline__ void mma_bf16(float* c,
                                         uint32_t a0, uint32_t a1, uint32_t a2, uint32_t a3,
                                         uint32_t b0, uint32_t b1) {
    asm("mma.sync.aligned.m16n8k16.row.col.f32.bf16.bf16.f32 "
        "{%0,%1,%2,%3},{%4,%5,%6,%7},{%8,%9},{%0,%1,%2,%3};"
        : "+f"(c[0]), "+f"(c[1]), "+f"(c[2]), "+f"(c[3])
        : "r"(a0), "r"(a1), "r"(a2), "r"(a3), "r"(b0), "r"(b1));
}

// ---------------------------------------------------------------------------
// Kernel 0: pack adj > 0 into bitmask
// ---------------------------------------------------------------------------
__global__ __launch_bounds__(256) void pack_kernel(const int* __restrict__ adj) {
    const int wid  = threadIdx.x >> 5;
    const int lane = threadIdx.x & 31;
    const int row  = blockIdx.x * 8 + wid;
    const int4* __restrict__ arow = (const int4*)(adj + (size_t)row * N_NODES);
    uint32_t* mrow = g_mask + (size_t)row * 256;
#pragma unroll 4
    for (int it = 0; it < 64; it++) {
        const int4 v = __ldcs(arow + it * 32 + lane);
        uint32_t b = (uint32_t)(v.x > 0) | ((uint32_t)(v.y > 0) << 1)
                   | ((uint32_t)(v.z > 0) << 2) | ((uint32_t)(v.w > 0) << 3);
        b <<= (lane & 7) * 4;
        b |= __shfl_xor_sync(0xFFFFFFFFu, b, 1);
        b |= __shfl_xor_sync(0xFFFFFFFFu, b, 2);
        b |= __shfl_xor_sync(0xFFFFFFFFu, b, 4);
        if ((lane & 7) == 0) mrow[it * 4 + (lane >> 3)] = b;
    }
}

// ---------------------------------------------------------------------------
// Kernel 1: Wh = h@W -> g_Bpack (bf16 m16n8k16 B-frag order, 2304B/kstep) ; s1,s2.
// ---------------------------------------------------------------------------
__global__ __launch_bounds__(64) void wh_kernel(const float* __restrict__ h,
                                                const float* __restrict__ W,
                                                const float* __restrict__ a) {
    __shared__ float sh[FIN];
    __shared__ float red1[2], red2[2];
    const int i = blockIdx.x;
    const int f = threadIdx.x;

    sh[f]      = h[(size_t)i * FIN + f];
    sh[f + 64] = h[(size_t)i * FIN + f + 64];
    __syncthreads();

    float acc0 = 0.f, acc1 = 0.f;
#pragma unroll
    for (int k = 0; k < FIN; k += 2) {
        acc0 = fmaf(sh[k],     W[k * FOUT + f],       acc0);
        acc1 = fmaf(sh[k + 1], W[(k + 1) * FOUT + f], acc1);
    }
    const float acc = acc0 + acc1;

    const int kstep = i >> 4;
    const int ko    = i & 15;
    const int pair  = ko >> 3;
    const int tig   = (ko & 7) >> 1;
    const int b     = ko & 1;
    __nv_bfloat16* bp = (__nv_bfloat16*)g_Bpack;
    const size_t sbase = (size_t)kstep * 1152;
    bp[sbase + ((f * 4 + tig) * 2 + pair) * 2 + b] = __float2bfloat16(acc);
    if (f < 8) {
        const float ov = (f == 0) ? 1.0f : 0.0f;  // col 64 = ones (denominator)
        bp[sbase + (((64 + f) * 4 + tig) * 2 + pair) * 2 + b] = __float2bfloat16(ov);
    }

    float v1 = acc * a[f];
    float v2 = acc * a[FOUT + f];
#pragma unroll
    for (int o = 16; o > 0; o >>= 1) {
        v1 += __shfl_xor_sync(0xFFFFFFFFu, v1, o);
        v2 += __shfl_xor_sync(0xFFFFFFFFu, v2, o);
    }
    if ((f & 31) == 0) { red1[f >> 5] = v1; red2[f >> 5] = v2; }
    __syncthreads();
    if (f == 0) {
        g_s1[i] = red1[0] + red1[1];
        g_s2[i] = red2[0] + red2[1];
    }
}

// ---------------------------------------------------------------------------
// Consumer: bf16 mma; warp owns mhalf(32 rows) x n(NF*8). B via LDG from L2.
// ---------------------------------------------------------------------------
template <int NF, int NHALF>
__device__ __forceinline__ void consumer_loop(uint32_t sbase, int mh, int lane,
                                              int half, int cta) {
    const int g   = lane >> 2;
    const int tig = lane & 3;
    const uint32_t aoff = (uint32_t)((mh * 32 + g) * 144 + tig * 4);
    const char* __restrict__ bglob = (const char*)g_Bpack
        + (size_t)half * 64 * B_TILE_BYTES + ((NHALF * 40 + g) * 4 + tig) * 8;

    float C[2][NF][4];
#pragma unroll
    for (int m = 0; m < 2; m++)
#pragma unroll
        for (int n = 0; n < NF; n++)
#pragma unroll
            for (int q = 0; q < 4; q++) C[m][n][q] = 0.f;

    int s = 0;
    for (int t = 0; t < JTILES; t++) {
        BAR_SYNC(1 + s);
        const uint32_t pb = sbase + S2_SZ + (uint32_t)s * STAGE_SZ + E_SZ;
        const char* __restrict__ bt = bglob + (size_t)t * B_TILE_BYTES;
#pragma unroll
        for (int ks = 0; ks < 4; ks++) {
            const uint32_t pa0 = pb + aoff + (uint32_t)ks * 32;
            const uint32_t pa1 = pa0 + 16u * 144;
            uint32_t A0[4], A1[4];
            A0[0] = lds32(pa0);       A0[1] = lds32(pa0 + 8u * 144);
            A0[2] = lds32(pa0 + 16);  A0[3] = lds32(pa0 + 8u * 144 + 16);
            A1[0] = lds32(pa1);       A1[1] = lds32(pa1 + 8u * 144);
            A1[2] = lds32(pa1 + 16);  A1[3] = lds32(pa1 + 8u * 144 + 16);
            const char* bk = bt + ks * 2304;
#pragma unroll
            for (int nf = 0; nf < NF; nf++) {
                const uint2 bf = *(const uint2*)(bk + nf * 256);
                mma_bf16(C[0][nf], A0[0], A0[1], A0[2], A0[3], bf.x, bf.y);
                mma_bf16(C[1][nf], A1[0], A1[1], A1[2], A1[3], bf.x, bf.y);
            }
        }
        if (t < JTILES - 3) BAR_ARRIVE(4 + s);
        s = (s == 2) ? 0 : s + 1;
    }

    // store partials (numerator cols 0..63, denominator col 64)
    float* pbase = g_part + (size_t)cta * TILE_M * PART_STRIDE;
#pragma unroll
    for (int m = 0; m < 2; m++) {
        const int r1 = mh * 32 + m * 16 + g;
        float* prow1 = pbase + r1 * PART_STRIDE;
        float* prow2 = prow1 + 8 * PART_STRIDE;
#pragma unroll
        for (int nf = 0; nf < NF; nf++) {
            const int gcol = NHALF * 40 + nf * 8 + 2 * tig;
            if (gcol < 64) {
                *(float2*)(prow1 + gcol) = make_float2(C[m][nf][0], C[m][nf][1]);
                *(float2*)(prow2 + gcol) = make_float2(C[m][nf][2], C[m][nf][3]);
            } else if (gcol == 64) {
                prow1[64] = C[m][nf][0];
                prow2[64] = C[m][nf][2];
            }
        }
    }
}

// ---------------------------------------------------------------------------
// Kernel 2: warp-specialized, grid 256 (128 rowblocks x 2 j-halves), 2 CTAs/SM.
//  warps 0-3: mma consumers.  warps 4-7: producers (cp.async efeat prefetch
//  2 tiles ahead -> exp from SMEM -> bf16 P tile).
// ---------------------------------------------------------------------------
__global__ __launch_bounds__(256, 2) void attn_mma_kernel(const float* __restrict__ efeat,
                                                          const float* __restrict__ a) {
    extern __shared__ char smem[];
    const uint32_t sbase = smem_u32(smem);
    const int tid  = threadIdx.x;
    const int wid  = tid >> 5;
    const int lane = tid & 31;
    const int cta  = blockIdx.x;
    const int i0   = (cta >> 1) * TILE_M;
    const int half = cta & 1;

    if (wid < 4) {
        const int mh = wid & 1;
        if ((wid >> 1) == 0) consumer_loop<5, 0>(sbase, mh, lane, half, cta);
        else                 consumer_loop<4, 1>(sbase, mh, lane, half, cta);
    } else {
        // ================= PRODUCER =================
        const int ptid = tid - 128;               // 0..127
        const int r    = ptid >> 1;               // row 0..63
        const int colq = ptid & 1;                // 32-col half of the 64-col tile
        const int grow = i0 + r;
        const float s1 = g_s1[grow];
        const float ae = a[2 * FOUT];
        const uint32_t* __restrict__ mrow = g_mask + (size_t)grow * 256 + half * 128;
        const char* __restrict__ esrc =
            (const char*)(efeat + (size_t)grow * N_NODES + half * 4096 + colq * 32);

        // s2 slice for this j-half into SMEM (resident whole kernel)
        {
            const float4* __restrict__ s2g = (const float4*)(g_s2 + half * 4096) + ptid * 8;
            const uint32_t dst = sbase + (uint32_t)ptid * 128;
#pragma unroll
            for (int q = 0; q < 8; q++) {
                const float4 v = s2g[q];
                sts128(dst + q * 16, __float_as_uint(v.x), __float_as_uint(v.y),
                       __float_as_uint(v.z), __float_as_uint(v.w));
            }
        }
        asm volatile("bar.sync 7, 128;" ::: "memory");

        // prologue: prefetch tiles 0,1 into stages 0,1
#pragma unroll
        for (int pt = 0; pt < 2; pt++) {
            const uint32_t edst = sbase + S2_SZ + (uint32_t)pt * STAGE_SZ + (uint32_t)ptid * 144;
            const char* es = esrc + (size_t)pt * 256;   // 64 cols * 4B per tile
#pragma unroll
            for (int c = 0; c < 8; c++) cp16(edst + c * 16, es + c * 16);
            CP_COMMIT();
        }

        uint32_t mw = __ldcs(mrow + colq);              // mask word for tile 0
        int s = 0;
        for (int t = 0; t < JTILES; t++) {
            CP_WAIT1();                                 // tile t's efeat arrived

            const uint32_t eb   = sbase + S2_SZ + (uint32_t)s * STAGE_SZ + (uint32_t)ptid * 144;
            const uint32_t s2b  = sbase + (uint32_t)t * 256 + (uint32_t)colq * 128;
            const uint32_t prow = sbase + S2_SZ + (uint32_t)s * STAGE_SZ + E_SZ
                                + (uint32_t)(r * 144 + colq * 64);
            uint32_t buf[4];
#pragma unroll
            for (int k = 0; k < 8; k++) {
                const float4 ev = lds128f(eb + k * 16);
                const float4 sv = lds128f(s2b + k * 16);
                float e0 = fmaf(ev.x, ae, s1 + sv.x);
                float e1 = fmaf(ev.y, ae, s1 + sv.y);
                float e2 = fmaf(ev.z, ae, s1 + sv.z);
                float e3 = fmaf(ev.w, ae, s1 + sv.w);
                e0 = fmaxf(e0, LRELU_ALPHA * e0);
                e1 = fmaxf(e1, LRELU_ALPHA * e1);
                e2 = fmaxf(e2, LRELU_ALPHA * e2);
                e3 = fmaxf(e3, LRELU_ALPHA * e3);
                const float p0 = (mw & (1u << (k * 4 + 0))) ? __expf(e0) : 0.f;
                const float p1 = (mw & (1u << (k * 4 + 1))) ? __expf(e1) : 0.f;
                const float p2 = (mw & (1u << (k * 4 + 2))) ? __expf(e2) : 0.f;
                const float p3 = (mw & (1u << (k * 4 + 3))) ? __expf(e3) : 0.f;
                const __nv_bfloat162 lo = __floats2bfloat162_rn(p0, p1);
                const __nv_bfloat162 hi = __floats2bfloat162_rn(p2, p3);
                buf[(k & 1) * 2 + 0] = *(const uint32_t*)&lo;
                buf[(k & 1) * 2 + 1] = *(const uint32_t*)&hi;
                if (k & 1)
                    sts128(prow + (uint32_t)(k >> 1) * 16, buf[0], buf[1], buf[2], buf[3]);
            }
            BAR_ARRIVE(1 + s);                          // publish P(t)

            if (t + 1 < JTILES)
                mw = __ldcs(mrow + (t + 1) * 2 + colq); // roll mask ahead

            // prefetch tile t+2 into stage (s+2)%3 once the consumer freed it
            const int s2g_ = (s == 0) ? 2 : s - 1;      // (s+2)%3
            if (t >= 1 && t < JTILES - 2) BAR_SYNC(4 + s2g_);
            if (t < JTILES - 2) {
                const uint32_t edst = sbase + S2_SZ + (uint32_t)s2g_ * STAGE_SZ
                                    + (uint32_t)ptid * 144;
                const char* es = esrc + (size_t)(t + 2) * 256;
#pragma unroll
                for (int c = 0; c < 8; c++) cp16(edst + c * 16, es + c * 16);
            }
            CP_COMMIT();                                // always commit (may be empty)
            s = (s == 2) ? 0 : s + 1;
        }
    }
}

// ---------------------------------------------------------------------------
// Kernel 3: combine the two j-half partials, divide, ELU, store.
// ---------------------------------------------------------------------------
__global__ __launch_bounds__(256) void combine_kernel(float* __restrict__ out) {
    const int idx = blockIdx.x * 256 + threadIdx.x;   // 8192*32
    const int i   = idx >> 5;
    const int f2  = idx & 31;
    const float* p0 = g_part + ((size_t)(i >> 6) * 2 * TILE_M + (i & 63)) * PART_STRIDE;
    const float* p1 = p0 + TILE_M * PART_STRIDE;
    const float inv = 1.f / (p0[64] + p1[64]);
    const float2 a0 = *(const float2*)(p0 + f2 * 2);
    const float2 b0 = *(const float2*)(p1 + f2 * 2);
    float v0 = (a0.x + b0.x) * inv;
    float v1 = (a0.y + b0.y) * inv;
    v0 = (v0 > 0.f) ? v0 : expm1f(v0);
    v1 = (v1 > 0.f) ? v1 : expm1f(v1);
    *(float2*)(out + (size_t)i * FOUT + f2 * 2) = make_float2(v0, v1);
}

// ---------------------------------------------------------------------------
extern "C" void kernel_launch(void* const* d_in, const int* in_sizes, int n_in,
                              void* d_out, int out_size) {
    const float* h     = (const float*)d_in[0];   // [8192,128]
    const int*   adj   = (const int*)  d_in[1];   // [8192,8192]
    const float* efeat = (const float*)d_in[2];   // [8192,8192]
    const float* W     = (const float*)d_in[3];   // [128,64]
    const float* a     = (const float*)d_in[4];   // [129,1]
    float* out = (float*)d_out;                   // [8192,64]

    cudaFuncSetAttribute(attn_mma_kernel,
                         cudaFuncAttributeMaxDynamicSharedMemorySize, SMEM_BYTES);

    pack_kernel<<<N_NODES / 8, 256>>>(adj);
    wh_kernel<<<N_NODES, 64>>>(h, W, a);
    attn_mma_kernel<<<256, 256, SMEM_BYTES>>>(efeat, a);
    combine_kernel<<<1024, 256>>>(out);
}

// round 9
// speedup vs baseline: 2.1468x; 1.0378x over previous
#include <cuda_runtime.h>
#include <cuda_bf16.h>
#include <math.h>
#include <cstdint>

#define N_NODES 8192
#define FOUT 64
#define TILE_M 64
#define JTILES 64
#define LRELU_ALPHA 0.2f

#define E_SZ 17408            // 64 rows x 272 B (256 data + 16 pad)
#define ERING 4
#define P_SZ 9216             // 64 rows x 144 B
#define S2_SZ 16384
#define OFF_E S2_SZ
#define OFF_P (S2_SZ + ERING * E_SZ)          // 86016
#define SMEM_BYTES (OFF_P + 2 * P_SZ)         // 104448
#define PART_STRIDE 66
#define B_TILE_BYTES 9216     // 4 ksteps x 2304 B

// ---------------- device scratch (no allocation allowed) -------------------
__device__ __align__(256) uint32_t g_Bpack[512 * 576 + 256];        // + OOB pad
__device__ __align__(256) uint32_t g_maskT[256 * N_NODES];          // [word][row]
__device__ __align__(256) float g_part[256 * TILE_M * PART_STRIDE];
__device__ float g_s1[N_NODES];
__device__ float g_s2[N_NODES];

// ---------------- helpers ----------------------------------------------------
__device__ __forceinline__ uint32_t smem_u32(const void* p) {
    uint32_t a;
    asm("{ .reg .u64 t; cvta.to.shared.u64 t, %1; cvt.u32.u64 %0, t; }" : "=r"(a) : "l"(p));
    return a;
}
__device__ __forceinline__ uint32_t lds32(uint32_t a) {
    uint32_t v; asm("ld.shared.b32 %0, [%1];" : "=r"(v) : "r"(a)); return v;
}
__device__ __forceinline__ float4 lds128f(uint32_t a) {
    float4 v;
    asm("ld.shared.v4.f32 {%0,%1,%2,%3}, [%4];"
        : "=f"(v.x), "=f"(v.y), "=f"(v.z), "=f"(v.w) : "r"(a));
    return v;
}
__device__ __forceinline__ void sts128(uint32_t a, uint32_t v0, uint32_t v1, uint32_t v2, uint32_t v3) {
    asm volatile("st.shared.v4.b32 [%0], {%1,%2,%3,%4};" :: "r"(a), "r"(v0), "r"(v1), "r"(v2), "r"(v3) : "memory");
}
__device__ __forceinline__ void cp16(uint32_t dst, const void* src) {
    asm volatile("cp.async.cg.shared.global [%0], [%1], 16;" :: "r"(dst), "l"(src) : "memory");
}
#define CP_COMMIT() asm volatile("cp.async.commit_group;" ::: "memory")
#define CP_WAIT3()  asm volatile("cp.async.wait_group 3;" ::: "memory")

__device__ __forceinline__ void mma_bf16(float* c,
                                         uint32_t a0, uint32_t a1, uint32_t a2, uint32_t a3,
                                         uint32_t b0, uint32_t b1) {
    asm("mma.sync.aligned.m16n8k16.row.col.f32.bf16.bf16.f32 "
        "{%0,%1,%2,%3},{%4,%5,%6,%7},{%8,%9},{%0,%1,%2,%3};"
        : "+f"(c[0]), "+f"(c[1]), "+f"(c[2]), "+f"(c[3])
        : "r"(a0), "r"(a1), "r"(a2), "r"(a3), "r"(b0), "r"(b1));
}

// ---------------------------------------------------------------------------
// Kernel 0: pack adj>0 into TRANSPOSED bitmask g_maskT[word][row]
// block: 8 warps; warp w handles 4 rows x 8 words; ballot builds words;
// SMEM transpose for coalesced stores.
// ---------------------------------------------------------------------------
__global__ __launch_bounds__(256) void pack_kernel(const int* __restrict__ adj) {
    __shared__ uint32_t sm[32][9];
    const int tid  = threadIdx.x;
    const int lane = tid & 31;
    const int widx = tid >> 5;
    const int rb = blockIdx.x >> 5;      // row block (32 rows)
    const int wb = blockIdx.x & 31;      // word block (8 words = 256 cols)
#pragma unroll
    for (int rr = 0; rr < 4; rr++) {
        const int row = rb * 32 + widx * 4 + rr;
        const int* __restrict__ arow = adj + (size_t)row * N_NODES + wb * 256;
#pragma unroll
        for (int w = 0; w < 8; w++) {
            const int v = __ldcs(arow + w * 32 + lane);
            const uint32_t b = __ballot_sync(0xFFFFFFFFu, v > 0);
            if (lane == w) sm[widx * 4 + rr][w] = b;
        }
    }
    __syncthreads();
    const int row = tid & 31, w = tid >> 5;
    g_maskT[(size_t)(wb * 8 + w) * N_NODES + rb * 32 + row] = sm[row][w];
}

// ---------------------------------------------------------------------------
// Kernel 1: Wh = h@W -> g_Bpack (bf16 m16n8k16 B-frag order); s1, s2.
// 512 blocks x 256 thr; W staged in SMEM once per block (16 rows/block).
// ---------------------------------------------------------------------------
__global__ __launch_bounds__(256) void wh_kernel(const float* __restrict__ h,
                                                 const float* __restrict__ W,
                                                 const float* __restrict__ a) {
    __shared__ float sW[128 * 64];
    __shared__ float shh[16 * 128];
    __shared__ float sr1[16][2], sr2[16][2];
    const int tid = threadIdx.x;
    const int i0  = blockIdx.x * 16;
#pragma unroll
    for (int q = 0; q < 8; q++)
        ((float4*)sW)[tid + q * 256] = ((const float4*)W)[tid + q * 256];
#pragma unroll
    for (int q = 0; q < 2; q++)
        ((float4*)shh)[tid + q * 256] = ((const float4*)(h + (size_t)i0 * 128))[tid + q * 256];
    __syncthreads();

    const int f  = tid & 63;
    const int rq = tid >> 6;             // rows rq*4 .. rq*4+3
    float acc[4] = {0.f, 0.f, 0.f, 0.f};
#pragma unroll 4
    for (int k = 0; k < 128; k++) {
        const float w = sW[k * 64 + f];
#pragma unroll
        for (int p = 0; p < 4; p++)
            acc[p] = fmaf(shh[(rq * 4 + p) * 128 + k], w, acc[p]);
    }

    const float a1 = a[f], a2 = a[64 + f];
    __nv_bfloat16* bp = (__nv_bfloat16*)g_Bpack;
#pragma unroll
    for (int p = 0; p < 4; p++) {
        const int i = i0 + rq * 4 + p;
        const int kstep = i >> 4, ko = i & 15;
        const int pair = ko >> 3, tig = (ko & 7) >> 1, b = ko & 1;
        const size_t sb = (size_t)kstep * 1152;
        bp[sb + ((f * 4 + tig) * 2 + pair) * 2 + b] = __float2bfloat16(acc[p]);
        if (f < 8)
            bp[sb + (((64 + f) * 4 + tig) * 2 + pair) * 2 + b] =
                __float2bfloat16(f == 0 ? 1.0f : 0.0f);
    }

    float v1[4], v2[4];
#pragma unroll
    for (int p = 0; p < 4; p++) { v1[p] = acc[p] * a1; v2[p] = acc[p] * a2; }
#pragma unroll
    for (int o = 16; o > 0; o >>= 1)
#pragma unroll
        for (int p = 0; p < 4; p++) {
            v1[p] += __shfl_xor_sync(0xFFFFFFFFu, v1[p], o);
            v2[p] += __shfl_xor_sync(0xFFFFFFFFu, v2[p], o);
        }
    if ((f & 31) == 0) {
        const int wh_ = f >> 5;
#pragma unroll
        for (int p = 0; p < 4; p++) {
            sr1[rq * 4 + p][wh_] = v1[p];
            sr2[rq * 4 + p][wh_] = v2[p];
        }
    }
    __syncthreads();
    if (tid < 16) {
        g_s1[i0 + tid] = sr1[tid][0] + sr1[tid][1];
        g_s2[i0 + tid] = sr2[tid][0] + sr2[tid][1];
    }
}

// ---------------------------------------------------------------------------
// Kernel 2: unified (no warp specialization). grid 256, 2 CTAs/SM.
// Per tile: all 256 threads compute P(t) (E via 4-deep cp.async ring),
// sync, all 8 warps MMA m16 slices. NF=5 uniform (5th frag discarded).
// ---------------------------------------------------------------------------
__global__ __launch_bounds__(256, 2) void attn_mma_kernel(const float* __restrict__ efeat,
                                                          const float* __restrict__ a) {
    extern __shared__ char smem[];
    const uint32_t sbase = smem_u32(smem);
    const int tid  = threadIdx.x;
    const int lane = tid & 31;
    const int wid  = tid >> 5;
    const int cta  = blockIdx.x;
    const int i0   = (cta >> 1) * TILE_M;
    const int half = cta & 1;

    // producer mapping: r = row, cg = 16-col group
    const int r  = tid & 63;
    const int cg = tid >> 6;
    const int grow = i0 + r;
    const float s1 = g_s1[grow];
    const float ae = a[2 * FOUT];
    const char* __restrict__ ebase =
        (const char*)(efeat + (size_t)grow * N_NODES + half * 4096) + cg * 64;
    const uint32_t eslot = sbase + OFF_E + (uint32_t)(r * 272 + cg * 64);
    const int mshift = (cg & 1) * 16;
    const uint32_t* __restrict__ mcol =
        g_maskT + (size_t)(half * 128 + (cg >> 1)) * N_NODES + grow;

    // consumer mapping: warp -> m-quarter (16 rows) x n-half
    const int g = lane >> 2, tig = lane & 3;
    const int mh = wid & 3, nh = wid >> 2;
    const uint32_t aoff = (uint32_t)((mh * 16 + g) * 144 + tig * 4);
    const char* __restrict__ bglob = (const char*)g_Bpack
        + (size_t)half * 64 * B_TILE_BYTES + ((nh * 40 + g) * 4 + tig) * 8;

    // s2 slice resident in SMEM
    {
        const float4* __restrict__ s2g = (const float4*)(g_s2 + half * 4096);
        const uint32_t dst = sbase + (uint32_t)tid * 64;
#pragma unroll
        for (int q = 0; q < 4; q++) {
            const float4 v = s2g[tid * 4 + q];
            sts128(dst + q * 16, __float_as_uint(v.x), __float_as_uint(v.y),
                   __float_as_uint(v.z), __float_as_uint(v.w));
        }
    }
    __syncthreads();

    // prologue: prefetch tiles 0..3
#pragma unroll
    for (int pt = 0; pt < 4; pt++) {
        const uint32_t edst = eslot + (uint32_t)pt * E_SZ;
#pragma unroll
        for (int k = 0; k < 4; k++) cp16(edst + k * 16, ebase + pt * 256 + k * 16);
        CP_COMMIT();
    }
    uint32_t mw = __ldcs(mcol);

    float C[5][4];
#pragma unroll
    for (int n = 0; n < 5; n++)
#pragma unroll
        for (int q = 0; q < 4; q++) C[n][q] = 0.f;

    for (int t = 0; t < JTILES; t++) {
        CP_WAIT3();
        __syncthreads();                       // E(t) visible; P buf (t&1) free

        // ---- compute P(t): 16 values per thread ----
        const uint32_t eb   = eslot + (uint32_t)(t & 3) * E_SZ;
        const uint32_t s2b  = sbase + (uint32_t)t * 256 + cg * 64;
        const uint32_t prow = sbase + OFF_P + (uint32_t)(t & 1) * P_SZ
                            + (uint32_t)(r * 144 + cg * 32);
        uint32_t buf[4];
#pragma unroll
        for (int k = 0; k < 4; k++) {
            const float4 ev = lds128f(eb + k * 16);
            const float4 sv = lds128f(s2b + k * 16);
            float e0 = fmaf(ev.x, ae, s1 + sv.x);
            float e1 = fmaf(ev.y, ae, s1 + sv.y);
            float e2 = fmaf(ev.z, ae, s1 + sv.z);
            float e3 = fmaf(ev.w, ae, s1 + sv.w);
            e0 = fmaxf(e0, LRELU_ALPHA * e0);
            e1 = fmaxf(e1, LRELU_ALPHA * e1);
            e2 = fmaxf(e2, LRELU_ALPHA * e2);
            e3 = fmaxf(e3, LRELU_ALPHA * e3);
            const float p0 = (mw & (1u << (mshift + k * 4 + 0))) ? __expf(e0) : 0.f;
            const float p1 = (mw & (1u << (mshift + k * 4 + 1))) ? __expf(e1) : 0.f;
            const float p2 = (mw & (1u << (mshift + k * 4 + 2))) ? __expf(e2) : 0.f;
            const float p3 = (mw & (1u << (mshift + k * 4 + 3))) ? __expf(e3) : 0.f;
            const __nv_bfloat162 lo = __floats2bfloat162_rn(p0, p1);
            const __nv_bfloat162 hi = __floats2bfloat162_rn(p2, p3);
            buf[(k & 1) * 2 + 0] = *(const uint32_t*)&lo;
            buf[(k & 1) * 2 + 1] = *(const uint32_t*)&hi;
            if (k & 1)
                sts128(prow + (uint32_t)(k >> 1) * 16, buf[0], buf[1], buf[2], buf[3]);
        }
        __syncthreads();                       // P(t) published

        // ---- prefetch E(t+4) into the slot just consumed ----
        if (t < JTILES - 4) {
            const uint32_t edst = eslot + (uint32_t)(t & 3) * E_SZ;
#pragma unroll
            for (int k = 0; k < 4; k++)
                cp16(edst + k * 16, ebase + (size_t)(t + 4) * 256 + k * 16);
        }
        CP_COMMIT();
        if (t < JTILES - 1) mw = __ldcs(mcol + (size_t)(t + 1) * 2 * N_NODES);

        // ---- MMA(t): each warp m16 x n40 ----
        const uint32_t pb = sbase + OFF_P + (uint32_t)(t & 1) * P_SZ;
        const char* __restrict__ bt = bglob + (size_t)t * B_TILE_BYTES;
#pragma unroll
        for (int ks = 0; ks < 4; ks++) {
            const uint32_t pa = pb + aoff + (uint32_t)ks * 32;
            const uint32_t A0 = lds32(pa);
            const uint32_t A1 = lds32(pa + 8u * 144);
            const uint32_t A2 = lds32(pa + 16);
            const uint32_t A3 = lds32(pa + 8u * 144 + 16);
            const char* bk = bt + ks * 2304;
#pragma unroll
            for (int nf = 0; nf < 5; nf++) {
                const uint2 bf = *(const uint2*)(bk + nf * 256);
                mma_bf16(C[nf], A0, A1, A2, A3, bf.x, bf.y);
            }
        }
    }

    // ---- partial store (cols >= 65 discarded) ----
    float* pbase = g_part + (size_t)cta * TILE_M * PART_STRIDE;
    float* prow1 = pbase + (mh * 16 + g) * PART_STRIDE;
    float* prow2 = prow1 + 8 * PART_STRIDE;
#pragma unroll
    for (int nf = 0; nf < 5; nf++) {
        const int gcol = nh * 40 + nf * 8 + 2 * tig;
        if (gcol < 64) {
            *(float2*)(prow1 + gcol) = make_float2(C[nf][0], C[nf][1]);
            *(float2*)(prow2 + gcol) = make_float2(C[nf][2], C[nf][3]);
        } else if (gcol == 64) {
            prow1[64] = C[nf][0];
            prow2[64] = C[nf][2];
        }
    }
}

// ---------------------------------------------------------------------------
// Kernel 3: combine the two j-half partials, divide, ELU, store.
// ---------------------------------------------------------------------------
__global__ __launch_bounds__(256) void combine_kernel(float* __restrict__ out) {
    const int idx = blockIdx.x * 256 + threadIdx.x;
    const int i   = idx >> 5;
    const int f2  = idx & 31;
    const float* p0 = g_part + ((size_t)(i >> 6) * 2 * TILE_M + (i & 63)) * PART_STRIDE;
    const float* p1 = p0 + TILE_M * PART_STRIDE;
    const float inv = 1.f / (p0[64] + p1[64]);
    const float2 a0 = *(const float2*)(p0 + f2 * 2);
    const float2 b0 = *(const float2*)(p1 + f2 * 2);
    float v0 = (a0.x + b0.x) * inv;
    float v1 = (a0.y + b0.y) * inv;
    v0 = (v0 > 0.f) ? v0 : expm1f(v0);
    v1 = (v1 > 0.f) ? v1 : expm1f(v1);
    *(float2*)(out + (size_t)i * FOUT + f2 * 2) = make_float2(v0, v1);
}

// ---------------------------------------------------------------------------
extern "C" void kernel_launch(void* const* d_in, const int* in_sizes, int n_in,
                              void* d_out, int out_size) {
    const float* h     = (const float*)d_in[0];
    const int*   adj   = (const int*)  d_in[1];
    const float* efeat = (const float*)d_in[2];
    const float* W     = (const float*)d_in[3];
    const float* a     = (const float*)d_in[4];
    float* out = (float*)d_out;

    cudaFuncSetAttribute(attn_mma_kernel,
                         cudaFuncAttributeMaxDynamicSharedMemorySize, SMEM_BYTES);

    pack_kernel<<<8192, 256>>>(adj);
    wh_kernel<<<512, 256>>>(h, W, a);
    attn_mma_kernel<<<256, 256, SMEM_BYTES>>>(efeat, a);
    combine_kernel<<<1024, 256>>>(out);
}

// round 10
// speedup vs baseline: 2.5854x; 1.2043x over previous
#include <cuda_runtime.h>
#include <cuda_bf16.h>
#include <math.h>
#include <cstdint>

#define N_NODES 8192
#define FOUT 64
#define TILE_M 64
#define JTILES 32            // per CTA: 32 tiles x 64 cols = 2048 cols (j-split = 4)
#define LRELU_ALPHA 0.2f

#define S2_SZ 8192           // 2048 floats (this CTA's j-quarter of s2)
#define P_SZ 9216            // 64 rows x 144 B (128 bf16 + 16 pad)
#define OFF_P S2_SZ
#define SMEM_BYTES (S2_SZ + 2 * P_SZ)   // 26624 -> 4 CTAs/SM
#define PART_STRIDE 66
#define B_TILE_BYTES 9216    // 4 ksteps x 2304 B

// ---------------- device scratch (no allocation allowed) -------------------
__device__ __align__(256) uint32_t g_Bpack[512 * 576 + 256];          // + OOB pad
__device__ __align__(256) uint32_t g_mask[N_NODES * 256];             // row-major
__device__ __align__(256) float g_part[512 * TILE_M * PART_STRIDE];  // 8.7 MB
__device__ float g_s1[N_NODES];
__device__ float g_s2[N_NODES];

// ---------------- helpers ----------------------------------------------------
__device__ __forceinline__ uint32_t smem_u32(const void* p) {
    uint32_t a;
    asm("{ .reg .u64 t; cvta.to.shared.u64 t, %1; cvt.u32.u64 %0, t; }" : "=r"(a) : "l"(p));
    return a;
}
__device__ __forceinline__ uint32_t lds32(uint32_t a) {
    uint32_t v; asm("ld.shared.b32 %0, [%1];" : "=r"(v) : "r"(a)); return v;
}
__device__ __forceinline__ float4 lds128f(uint32_t a) {
    float4 v;
    asm("ld.shared.v4.f32 {%0,%1,%2,%3}, [%4];"
        : "=f"(v.x), "=f"(v.y), "=f"(v.z), "=f"(v.w) : "r"(a));
    return v;
}
__device__ __forceinline__ void sts64(uint32_t a, uint32_t v0, uint32_t v1) {
    asm volatile("st.shared.v2.b32 [%0], {%1,%2};" :: "r"(a), "r"(v0), "r"(v1) : "memory");
}
__device__ __forceinline__ void sts128(uint32_t a, uint32_t v0, uint32_t v1, uint32_t v2, uint32_t v3) {
    asm volatile("st.shared.v4.b32 [%0], {%1,%2,%3,%4};" :: "r"(a), "r"(v0), "r"(v1), "r"(v2), "r"(v3) : "memory");
}
__device__ __forceinline__ void mma_bf16(float* c,
                                         uint32_t a0, uint32_t a1, uint32_t a2, uint32_t a3,
                                         uint32_t b0, uint32_t b1) {
    asm("mma.sync.aligned.m16n8k16.row.col.f32.bf16.bf16.f32 "
        "{%0,%1,%2,%3},{%4,%5,%6,%7},{%8,%9},{%0,%1,%2,%3};"
        : "+f"(c[0]), "+f"(c[1]), "+f"(c[2]), "+f"(c[3])
        : "r"(a0), "r"(a1), "r"(a2), "r"(a3), "r"(b0), "r"(b1));
}

// ---------------------------------------------------------------------------
// Kernel 0: pack adj>0 into row-major bitmask g_mask[row][word] via ballot.
// ---------------------------------------------------------------------------
__global__ __launch_bounds__(256) void pack_kernel(const int* __restrict__ adj) {
    __shared__ uint32_t sm[32][9];
    const int tid  = threadIdx.x;
    const int lane = tid & 31;
    const int widx = tid >> 5;
    const int rb = blockIdx.x >> 5;      // 32-row block
    const int wb = blockIdx.x & 31;      // 8-word block (256 cols)
#pragma unroll
    for (int rr = 0; rr < 4; rr++) {
        const int row = rb * 32 + widx * 4 + rr;
        const int* __restrict__ arow = adj + (size_t)row * N_NODES + wb * 256;
#pragma unroll
        for (int w = 0; w < 8; w++) {
            const int v = __ldcs(arow + w * 32 + lane);
            const uint32_t b = __ballot_sync(0xFFFFFFFFu, v > 0);
            if (lane == w) sm[widx * 4 + rr][w] = b;
        }
    }
    __syncthreads();
    const int row = tid >> 3, w = tid & 7;
    g_mask[(size_t)(rb * 32 + row) * 256 + wb * 8 + w] = sm[row][w];
}

// ---------------------------------------------------------------------------
// Kernel 1: Wh = h@W -> g_Bpack (bf16 m16n8k16 B-frag order); s1, s2.
// ---------------------------------------------------------------------------
__global__ __launch_bounds__(256) void wh_kernel(const float* __restrict__ h,
                                                 const float* __restrict__ W,
                                                 const float* __restrict__ a) {
    __shared__ float sW[128 * 64];
    __shared__ float shh[16 * 128];
    __shared__ float sr1[16][2], sr2[16][2];
    const int tid = threadIdx.x;
    const int i0  = blockIdx.x * 16;
#pragma unroll
    for (int q = 0; q < 8; q++)
        ((float4*)sW)[tid + q * 256] = ((const float4*)W)[tid + q * 256];
#pragma unroll
    for (int q = 0; q < 2; q++)
        ((float4*)shh)[tid + q * 256] = ((const float4*)(h + (size_t)i0 * 128))[tid + q * 256];
    __syncthreads();

    const int f  = tid & 63;
    const int rq = tid >> 6;
    float acc[4] = {0.f, 0.f, 0.f, 0.f};
#pragma unroll 4
    for (int k = 0; k < 128; k++) {
        const float w = sW[k * 64 + f];
#pragma unroll
        for (int p = 0; p < 4; p++)
            acc[p] = fmaf(shh[(rq * 4 + p) * 128 + k], w, acc[p]);
    }

    const float a1 = a[f], a2 = a[64 + f];
    __nv_bfloat16* bp = (__nv_bfloat16*)g_Bpack;
#pragma unroll
    for (int p = 0; p < 4; p++) {
        const int i = i0 + rq * 4 + p;
        const int kstep = i >> 4, ko = i & 15;
        const int pair = ko >> 3, tig = (ko & 7) >> 1, b = ko & 1;
        const size_t sb = (size_t)kstep * 1152;
        bp[sb + ((f * 4 + tig) * 2 + pair) * 2 + b] = __float2bfloat16(acc[p]);
        if (f < 8)
            bp[sb + (((64 + f) * 4 + tig) * 2 + pair) * 2 + b] =
                __float2bfloat16(f == 0 ? 1.0f : 0.0f);
    }

    float v1[4], v2[4];
#pragma unroll
    for (int p = 0; p < 4; p++) { v1[p] = acc[p] * a1; v2[p] = acc[p] * a2; }
#pragma unroll
    for (int o = 16; o > 0; o >>= 1)
#pragma unroll
        for (int p = 0; p < 4; p++) {
            v1[p] += __shfl_xor_sync(0xFFFFFFFFu, v1[p], o);
            v2[p] += __shfl_xor_sync(0xFFFFFFFFu, v2[p], o);
        }
    if ((f & 31) == 0) {
        const int wh_ = f >> 5;
#pragma unroll
        for (int p = 0; p < 4; p++) {
            sr1[rq * 4 + p][wh_] = v1[p];
            sr2[rq * 4 + p][wh_] = v2[p];
        }
    }
    __syncthreads();
    if (tid < 16) {
        g_s1[i0 + tid] = sr1[tid][0] + sr1[tid][1];
        g_s2[i0 + tid] = sr2[tid][0] + sr2[tid][1];
    }
}

// ---------------------------------------------------------------------------
// Kernel 2: unified, register-prefetched E. grid 512 (128 rowblocks x 4 jq),
// 4 CTAs/SM. Per tile: all threads compute P(t) (E in regs, half-warp-
// contiguous loads), ONE sync, all warps MMA.
// ---------------------------------------------------------------------------
__global__ __launch_bounds__(256, 4) void attn_mma_kernel(const float* __restrict__ efeat,
                                                          const float* __restrict__ a) {
    extern __shared__ char smem[];
    const uint32_t sbase = smem_u32(smem);
    const int tid  = threadIdx.x;
    const int lane = tid & 31;
    const int wid  = tid >> 5;
    const int cta  = blockIdx.x;
    const int i0   = (cta >> 2) * TILE_M;
    const int jq   = cta & 3;

    // -------- producer mapping: 4 pieces of (row, 4 cols) per thread --------
    const int ls   = lane >> 4;            // 0/1: row within half-warp pair
    const int cf   = lane & 15;            // float4 col index (cols cf*4..cf*4+3)
    const int rowb = wid * 8 + ls;         // piece k -> row rowb + 2k
    const int c    = cf * 4;
    const int wsel = cf >> 3;              // mask word within tile
    const int bsh  = (lane & 7) * 4;       // bit offset base
    const int grow0 = i0 + rowb;
    const float ae = a[2 * FOUT];

    float s1r[4];
#pragma unroll
    for (int k = 0; k < 4; k++) s1r[k] = g_s1[grow0 + 2 * k];

    const float4* __restrict__ ep =
        (const float4*)(efeat + (size_t)grow0 * N_NODES + jq * 2048) + cf;
    const uint32_t* __restrict__ mbase =
        g_mask + (size_t)grow0 * 256 + jq * 64 + wsel;

    // -------- consumer mapping --------
    const int g = lane >> 2, tig = lane & 3;
    const int mh = wid & 3, nh = wid >> 2;
    const uint32_t aoff = (uint32_t)((mh * 16 + g) * 144 + tig * 4);
    const char* __restrict__ bglob = (const char*)g_Bpack
        + (size_t)jq * 32 * B_TILE_BYTES + ((nh * 40 + g) * 4 + tig) * 8;

    // -------- s2 slice to SMEM --------
    {
        const float4* __restrict__ s2g = (const float4*)(g_s2 + jq * 2048);
        const uint32_t dst = sbase + (uint32_t)tid * 32;
#pragma unroll
        for (int q = 0; q < 2; q++) {
            const float4 v = s2g[tid * 2 + q];
            sts128(dst + q * 16, __float_as_uint(v.x), __float_as_uint(v.y),
                   __float_as_uint(v.z), __float_as_uint(v.w));
        }
    }
    __syncthreads();

    // -------- preload E(0), mask(0) --------
    float4 e[4];
    uint32_t mw[4];
#pragma unroll
    for (int k = 0; k < 4; k++) {
        e[k]  = __ldcs(ep + k * 4096);          // 2 rows * 8192 floats / 4
        mw[k] = __ldg(mbase + k * 512);
    }

    float C[5][4];
#pragma unroll
    for (int n = 0; n < 5; n++)
#pragma unroll
        for (int q = 0; q < 4; q++) C[n][q] = 0.f;

    for (int t = 0; t < JTILES; t++) {
        // ---- compute P(t) from registers ----
        const uint32_t pbuf = sbase + OFF_P + (uint32_t)(t & 1) * P_SZ;
        const float4 sv = *(const float4*)(smem + (uint32_t)t * 256 + c * 4);
#pragma unroll
        for (int k = 0; k < 4; k++) {
            const float4 ev = e[k];
            const float s1 = s1r[k];
            float e0 = fmaf(ev.x, ae, s1 + sv.x);
            float e1 = fmaf(ev.y, ae, s1 + sv.y);
            float e2 = fmaf(ev.z, ae, s1 + sv.z);
            float e3 = fmaf(ev.w, ae, s1 + sv.w);
            e0 = fmaxf(e0, LRELU_ALPHA * e0);
            e1 = fmaxf(e1, LRELU_ALPHA * e1);
            e2 = fmaxf(e2, LRELU_ALPHA * e2);
            e3 = fmaxf(e3, LRELU_ALPHA * e3);
            const uint32_t m = mw[k] >> bsh;
            const float p0 = (m & 1u) ? __expf(e0) : 0.f;
            const float p1 = (m & 2u) ? __expf(e1) : 0.f;
            const float p2 = (m & 4u) ? __expf(e2) : 0.f;
            const float p3 = (m & 8u) ? __expf(e3) : 0.f;
            const __nv_bfloat162 lo = __floats2bfloat162_rn(p0, p1);
            const __nv_bfloat162 hi = __floats2bfloat162_rn(p2, p3);
            sts64(pbuf + (uint32_t)((rowb + 2 * k) * 144 + c * 2),
                  *(const uint32_t*)&lo, *(const uint32_t*)&hi);
        }

        // ---- prefetch E(t+1), mask(t+1) ----
        if (t < JTILES - 1) {
#pragma unroll
            for (int k = 0; k < 4; k++) {
                e[k]  = __ldcs(ep + k * 4096 + (t + 1) * 16);
                mw[k] = __ldg(mbase + k * 512 + (t + 1) * 2);
            }
        }

        __syncthreads();                        // publish P(t)

        // ---- MMA(t): each warp m16 x n40 ----
        const char* __restrict__ bt = bglob + (size_t)t * B_TILE_BYTES;
#pragma unroll
        for (int ks = 0; ks < 4; ks++) {
            const uint32_t pa = pbuf + aoff + (uint32_t)ks * 32;
            const uint32_t A0 = lds32(pa);
            const uint32_t A1 = lds32(pa + 8u * 144);
            const uint32_t A2 = lds32(pa + 16);
            const uint32_t A3 = lds32(pa + 8u * 144 + 16);
            const char* bk = bt + ks * 2304;
#pragma unroll
            for (int nf = 0; nf < 5; nf++) {
                const uint2 bf = *(const uint2*)(bk + nf * 256);
                mma_bf16(C[nf], A0, A1, A2, A3, bf.x, bf.y);
            }
        }
    }

    // ---- partial store ----
    float* pbase = g_part + (size_t)cta * TILE_M * PART_STRIDE;
    float* prow1 = pbase + (mh * 16 + g) * PART_STRIDE;
    float* prow2 = prow1 + 8 * PART_STRIDE;
#pragma unroll
    for (int nf = 0; nf < 5; nf++) {
        const int gcol = nh * 40 + nf * 8 + 2 * tig;
        if (gcol < 64) {
            *(float2*)(prow1 + gcol) = make_float2(C[nf][0], C[nf][1]);
            *(float2*)(prow2 + gcol) = make_float2(C[nf][2], C[nf][3]);
        } else if (gcol == 64) {
            prow1[64] = C[nf][0];
            prow2[64] = C[nf][2];
        }
    }
}

// ---------------------------------------------------------------------------
// Kernel 3: combine the four j-quarter partials, divide, ELU, store.
// ---------------------------------------------------------------------------
__global__ __launch_bounds__(256) void combine_kernel(float* __restrict__ out) {
    const int idx = blockIdx.x * 256 + threadIdx.x;
    const int i   = idx >> 5;
    const int f2  = idx & 31;
    const float* base = g_part + (size_t)(i >> 6) * 4 * TILE_M * PART_STRIDE
                      + (i & 63) * PART_STRIDE;
    float den = 0.f, nx = 0.f, ny = 0.f;
#pragma unroll
    for (int q = 0; q < 4; q++) {
        const float* p = base + (size_t)q * TILE_M * PART_STRIDE;
        den += p[64];
        const float2 v = *(const float2*)(p + f2 * 2);
        nx += v.x;
        ny += v.y;
    }
    const float inv = 1.f / den;
    float v0 = nx * inv, v1 = ny * inv;
    v0 = (v0 > 0.f) ? v0 : expm1f(v0);
    v1 = (v1 > 0.f) ? v1 : expm1f(v1);
    *(float2*)(out + (size_t)i * FOUT + f2 * 2) = make_float2(v0, v1);
}

// ---------------------------------------------------------------------------
extern "C" void kernel_launch(void* const* d_in, const int* in_sizes, int n_in,
                              void* d_out, int out_size) {
    const float* h     = (const float*)d_in[0];
    const int*   adj   = (const int*)  d_in[1];
    const float* efeat = (const float*)d_in[2];
    const float* W     = (const float*)d_in[3];
    const float* a     = (const float*)d_in[4];
    float* out = (float*)d_out;

    cudaFuncSetAttribute(attn_mma_kernel,
                         cudaFuncAttributeMaxDynamicSharedMemorySize, SMEM_BYTES);

    pack_kernel<<<8192, 256>>>(adj);
    wh_kernel<<<512, 256>>>(h, W, a);
    attn_mma_kernel<<<512, 256, SMEM_BYTES>>>(efeat, a);
    combine_kernel<<<1024, 256>>>(out);
}